// round 9
// baseline (speedup 1.0000x reference)
#include <cuda_runtime.h>
#include <cuda_bf16.h>

// Chamfer distance, B=16, N=M=2048, D=3 — SHARED-PAIR kernel.
// Key insight: dir0 (pred->targ) mins are ROW mins and dir1 (targ->pred) mins
// are COL mins of the SAME distance matrix. Evaluate each of the 67M unique
// pairs once, reduce both ways -> halves the fma-pipe work vs brute force.
//
// Per block (grid 32 i-tiles x 16 batches): all 2048 targets live in lane
// registers (8 packed pairs/lane x 32 lanes x 4 warps), loop over 64 preds.
// Per packed pair per pred: t = yy - 2 x.y via 3x fma.rn.f32x2 (row value,
// xx added at the end), u = t + xx via add.rn.f32x2 = full d^2 (col value:
// min_i u = yy + min_i(xx - 2s), complete -> no finalize add).
// Rows: in-lane FMNMX tree + warp shuffle + cross-warp smem -> block sum ->
// atomicAdd into g_rowsum. Cols: register accumulators -> atomicMax on
// order-reversed float encoding (identity 0 => zero-init scratch, reset by
// finalize -> graph-replay safe). Finalize kernel (16x2048 words) decodes,
// sums cols, adds g_rowsum, writes out[0], resets scratch.

#define CB_NPTS   2048
#define CB_B      16
#define CB_TPB    128
#define CB_TI     64                      // preds per block
#define CB_ITILES (CB_NPTS / CB_TI)       // 32
#define CB_PPL    8                       // packed target-pairs per lane

__device__ unsigned g_col[CB_B * CB_NPTS];  // encR col minima; 0 = identity
__device__ float    g_rowsum;               // zero-init; reset by finalize

__device__ __forceinline__ unsigned long long f32x2_fma(
    unsigned long long a, unsigned long long b, unsigned long long c) {
    unsigned long long d;
    asm("fma.rn.f32x2 %0, %1, %2, %3;" : "=l"(d) : "l"(a), "l"(b), "l"(c));
    return d;
}
__device__ __forceinline__ unsigned long long f32x2_add(
    unsigned long long a, unsigned long long b) {
    unsigned long long d;
    asm("add.rn.f32x2 %0, %1, %2;" : "=l"(d) : "l"(a), "l"(b));
    return d;
}
__device__ __forceinline__ void f32x2_unpack(unsigned long long v, float& lo, float& hi) {
    asm("mov.b64 {%0, %1}, %2;" : "=f"(lo), "=f"(hi) : "l"(v));
}
__device__ __forceinline__ unsigned long long f32x2_pack(float lo, float hi) {
    unsigned long long v;
    asm("mov.b64 %0, {%1, %2};" : "=l"(v) : "f"(lo), "f"(hi));
    return v;
}

// Order-REVERSED encode: smaller float -> LARGER code; max-identity = 0.
__device__ __forceinline__ unsigned encR(float f) {
    unsigned u = __float_as_uint(f);
    unsigned e = (u & 0x80000000u) ? ~u : (u | 0x80000000u);
    return ~e;
}
__device__ __forceinline__ float decR(unsigned r) {
    unsigned e = ~r;
    return (e & 0x80000000u) ? __uint_as_float(e ^ 0x80000000u)
                             : __uint_as_float(~e);
}

__global__ __launch_bounds__(CB_TPB)
void chamfer_main(const float* __restrict__ preds,
                  const float* __restrict__ targs,
                  float* __restrict__ out)
{
    __shared__ unsigned long long sPack[1024 * 4];  // packed targ pairs (32KB)
    __shared__ float4 sQ[CB_TI];                    // (x0,x1,x2,|x|^2)
    __shared__ float  sRow[CB_TI * 4];              // per-warp row mins

    const int b   = blockIdx.y;
    const int tid = threadIdx.x;
    const int wid = tid >> 5;
    const int ln  = tid & 31;

    if (blockIdx.x == 0 && blockIdx.y == 0 && tid == 0)
        out[0] = 0.0f;    // finalize runs after us in stream order

    // ---- stage ALL 2048 targets as packed, pre-scaled pairs ----
    const float* tB = targs + (size_t)b * CB_NPTS * 3;
    for (int pp = tid; pp < 1024; pp += CB_TPB) {
        const float* r = tB + pp * 6;
        float a0 = r[0], a1 = r[1], a2 = r[2];
        float c0 = r[3], c1 = r[4], c2 = r[5];
        sPack[pp * 4 + 0] = f32x2_pack(-2.0f * a0, -2.0f * c0);
        sPack[pp * 4 + 1] = f32x2_pack(-2.0f * a1, -2.0f * c1);
        sPack[pp * 4 + 2] = f32x2_pack(-2.0f * a2, -2.0f * c2);
        sPack[pp * 4 + 3] = f32x2_pack(fmaf(a0, a0, fmaf(a1, a1, a2 * a2)),
                                       fmaf(c0, c0, fmaf(c1, c1, c2 * c2)));
    }
    // ---- stage this block's 64 preds with |x|^2 ----
    const float* pB = preds + (size_t)b * CB_NPTS * 3;
    if (tid < CB_TI) {
        int i = blockIdx.x * CB_TI + tid;
        float x0 = pB[i * 3 + 0];
        float x1 = pB[i * 3 + 1];
        float x2 = pB[i * 3 + 2];
        sQ[tid] = make_float4(x0, x1, x2, fmaf(x0, x0, fmaf(x1, x1, x2 * x2)));
    }
    __syncthreads();

    // ---- pull this lane's 8 packed target pairs into registers ----
    unsigned long long rax[CB_PPL], ray[CB_PPL], rbx[CB_PPL], rby[CB_PPL];
    #pragma unroll
    for (int r = 0; r < CB_PPL; ++r) {
        int pp = wid * 256 + r * 32 + ln;
        rax[r] = sPack[pp * 4 + 0];
        ray[r] = sPack[pp * 4 + 1];
        rbx[r] = sPack[pp * 4 + 2];
        rby[r] = sPack[pp * 4 + 3];
    }

    float cmin[2 * CB_PPL];
    #pragma unroll
    for (int r = 0; r < 2 * CB_PPL; ++r) cmin[r] = 3.402823466e38f;

    // ---- main loop: 64 preds x 16 lane-targets ----
    for (int i = 0; i < CB_TI; ++i) {
        float4 q = sQ[i];                                   // LDS.128 broadcast
        unsigned long long q0 = f32x2_pack(q.x, q.x);
        unsigned long long q1 = f32x2_pack(q.y, q.y);
        unsigned long long q2 = f32x2_pack(q.z, q.z);
        unsigned long long xxp = f32x2_pack(q.w, q.w);

        float rm0 = 3.402823466e38f, rm1 = 3.402823466e38f;
        #pragma unroll
        for (int r = 0; r < CB_PPL; ++r) {
            unsigned long long t = f32x2_fma(q2, rbx[r], rby[r]);
            t = f32x2_fma(q1, ray[r], t);
            t = f32x2_fma(q0, rax[r], t);      // t = yy - 2 x.y (2 targs)
            unsigned long long u = f32x2_add(t, xxp);   // u = d^2 (2 targs)
            float tl, th, ul, uh;
            f32x2_unpack(t, tl, th);
            f32x2_unpack(u, ul, uh);
            rm0 = fminf(rm0, tl);
            rm1 = fminf(rm1, th);
            cmin[2 * r]     = fminf(cmin[2 * r],     ul);
            cmin[2 * r + 1] = fminf(cmin[2 * r + 1], uh);
        }
        float rm = fminf(rm0, rm1);
        #pragma unroll
        for (int o = 16; o > 0; o >>= 1)
            rm = fminf(rm, __shfl_xor_sync(0xffffffffu, rm, o));
        if (ln == 0) sRow[i * 4 + wid] = rm;
    }

    // ---- publish col minima (REDG.MAX on reversed encoding) ----
    unsigned* gc = g_col + (size_t)b * CB_NPTS;
    #pragma unroll
    for (int r = 0; r < CB_PPL; ++r) {
        int pp = wid * 256 + r * 32 + ln;
        atomicMax(&gc[2 * pp],     encR(cmin[2 * r]));
        atomicMax(&gc[2 * pp + 1], encR(cmin[2 * r + 1]));
    }

    __syncthreads();

    // ---- row side: combine 4 warps, add |x|^2, sum, one atomic per warp ----
    if (tid < CB_TI) {
        float m = fminf(fminf(sRow[tid * 4 + 0], sRow[tid * 4 + 1]),
                        fminf(sRow[tid * 4 + 2], sRow[tid * 4 + 3]));
        float val = sQ[tid].w + m;
        #pragma unroll
        for (int o = 16; o > 0; o >>= 1)
            val += __shfl_down_sync(0xffffffffu, val, o);
        if (ln == 0) atomicAdd(&g_rowsum, val);
    }
}

__global__ __launch_bounds__(256)
void chamfer_finalize(float* __restrict__ out)
{
    __shared__ float sRed[8];
    const int b = blockIdx.y;
    const int half = blockIdx.x;           // 2 blocks per batch
    unsigned* gc = g_col + (size_t)b * CB_NPTS + half * (CB_NPTS / 2);

    float acc = 0.0f;
    for (int j = threadIdx.x; j < CB_NPTS / 2; j += 256) {
        acc += decR(gc[j]);
        gc[j] = 0u;                        // reset identity for next replay
    }
    #pragma unroll
    for (int o = 16; o > 0; o >>= 1)
        acc += __shfl_down_sync(0xffffffffu, acc, o);
    if ((threadIdx.x & 31) == 0) sRed[threadIdx.x >> 5] = acc;
    __syncthreads();
    if (threadIdx.x < 32) {
        float v2 = (threadIdx.x < 8) ? sRed[threadIdx.x] : 0.0f;
        #pragma unroll
        for (int o = 4; o > 0; o >>= 1)
            v2 += __shfl_down_sync(0xffffffffu, v2, o);
        if (threadIdx.x == 0) {
            if (blockIdx.x == 0 && blockIdx.y == 0) {
                v2 += g_rowsum;            // consume row-side sum
                g_rowsum = 0.0f;           // reset for next replay
            }
            atomicAdd(out, v2);
        }
    }
}

extern "C" void kernel_launch(void* const* d_in, const int* in_sizes, int n_in,
                              void* d_out, int out_size) {
    const float* preds = (const float*)d_in[0];
    const float* targs = (const float*)d_in[1];
    float* out = (float*)d_out;

    dim3 gridM(CB_ITILES, CB_B);   // (32, 16) = 512 blocks
    chamfer_main<<<gridM, CB_TPB>>>(preds, targs, out);

    dim3 gridF(2, CB_B);           // 32 blocks
    chamfer_finalize<<<gridF, 256>>>(out);
}

// round 10
// speedup vs baseline: 1.1454x; 1.1454x over previous
#include <cuda_runtime.h>
#include <cuda_bf16.h>

// Chamfer distance, B=16, N=M=2048, D=3 — shared-pair kernel v2.
// Each of the 67M unique (pred,targ) distances is evaluated ONCE; row mins
// (pred->targ) and col mins (targ->pred) are reduced from the same values.
// R10 deltas vs R9: TPB 256 (27 warps/SM), finalize 256 blocks (was 32, pure
// latency), row warp-min via REDUX.MIN.U32 on order-preserving encoding
// (replaces 5x SHFL chain).
//
// Per block (32 i-tiles x 16 batches): all 2048 targets in lane registers
// (4 packed pairs/lane x 32 lanes x 8 warps), loop over 64 preds.
// Inner per packed pair: t = yy - 2x.y (3x fma.rn.f32x2, refs pre-scaled),
// u = t + xx (add.rn.f32x2) = full d^2 for the col side.
// Cols: register mins -> atomicMax on order-REVERSED encoding (identity 0 =>
// zero-init __device__ scratch, reset by finalize -> graph-replay safe).
// Rows: REDUX-min per warp -> smem -> block combine -> atomicAdd(g_rowsum).

#define CB_NPTS   2048
#define CB_B      16
#define CB_TPB    256
#define CB_NW     (CB_TPB / 32)           // 8 warps
#define CB_TI     64                      // preds per block
#define CB_ITILES (CB_NPTS / CB_TI)       // 32
#define CB_PPL    4                       // packed target-pairs per lane

__device__ unsigned g_col[CB_B * CB_NPTS];  // encR col minima; 0 = identity
__device__ float    g_rowsum;               // zero-init; reset by finalize

__device__ __forceinline__ unsigned long long f32x2_fma(
    unsigned long long a, unsigned long long b, unsigned long long c) {
    unsigned long long d;
    asm("fma.rn.f32x2 %0, %1, %2, %3;" : "=l"(d) : "l"(a), "l"(b), "l"(c));
    return d;
}
__device__ __forceinline__ unsigned long long f32x2_add(
    unsigned long long a, unsigned long long b) {
    unsigned long long d;
    asm("add.rn.f32x2 %0, %1, %2;" : "=l"(d) : "l"(a), "l"(b));
    return d;
}
__device__ __forceinline__ void f32x2_unpack(unsigned long long v, float& lo, float& hi) {
    asm("mov.b64 {%0, %1}, %2;" : "=f"(lo), "=f"(hi) : "l"(v));
}
__device__ __forceinline__ unsigned long long f32x2_pack(float lo, float hi) {
    unsigned long long v;
    asm("mov.b64 %0, {%1, %2};" : "=l"(v) : "f"(lo), "f"(hi));
    return v;
}

// Order-PRESERVING encode (for REDUX.MIN): smaller float -> smaller code.
__device__ __forceinline__ unsigned encP(float f) {
    unsigned u = __float_as_uint(f);
    unsigned m = (unsigned)(((int)u) >> 31) | 0x80000000u;
    return u ^ m;
}
__device__ __forceinline__ float decP(unsigned e) {
    unsigned m = (~(unsigned)(((int)e) >> 31)) | 0x80000000u;
    return __uint_as_float(e ^ m);
}
// Order-REVERSED encode (for atomicMax with zero identity).
__device__ __forceinline__ unsigned encR(float f) { return ~encP(f); }
__device__ __forceinline__ float decR(unsigned r) { return decP(~r); }

__global__ __launch_bounds__(CB_TPB)
void chamfer_main(const float* __restrict__ preds,
                  const float* __restrict__ targs,
                  float* __restrict__ out)
{
    __shared__ unsigned long long sPack[1024 * 4];  // packed targ pairs (32KB)
    __shared__ float4   sQ[CB_TI];                  // (x0,x1,x2,|x|^2)
    __shared__ unsigned sRowE[CB_TI * CB_NW];       // per-warp encoded row mins

    const int b   = blockIdx.y;
    const int tid = threadIdx.x;
    const int wid = tid >> 5;
    const int ln  = tid & 31;

    if (blockIdx.x == 0 && blockIdx.y == 0 && tid == 0)
        out[0] = 0.0f;    // finalize runs after us in stream order

    // ---- stage ALL 2048 targets as packed, pre-scaled pairs ----
    const float* tB = targs + (size_t)b * CB_NPTS * 3;
    for (int pp = tid; pp < 1024; pp += CB_TPB) {
        const float* r = tB + pp * 6;
        float a0 = r[0], a1 = r[1], a2 = r[2];
        float c0 = r[3], c1 = r[4], c2 = r[5];
        sPack[pp * 4 + 0] = f32x2_pack(-2.0f * a0, -2.0f * c0);
        sPack[pp * 4 + 1] = f32x2_pack(-2.0f * a1, -2.0f * c1);
        sPack[pp * 4 + 2] = f32x2_pack(-2.0f * a2, -2.0f * c2);
        sPack[pp * 4 + 3] = f32x2_pack(fmaf(a0, a0, fmaf(a1, a1, a2 * a2)),
                                       fmaf(c0, c0, fmaf(c1, c1, c2 * c2)));
    }
    // ---- stage this block's 64 preds with |x|^2 ----
    const float* pB = preds + (size_t)b * CB_NPTS * 3;
    if (tid < CB_TI) {
        int i = blockIdx.x * CB_TI + tid;
        float x0 = pB[i * 3 + 0];
        float x1 = pB[i * 3 + 1];
        float x2 = pB[i * 3 + 2];
        sQ[tid] = make_float4(x0, x1, x2, fmaf(x0, x0, fmaf(x1, x1, x2 * x2)));
    }
    __syncthreads();

    // ---- pull this lane's 4 packed target pairs into registers ----
    unsigned long long rax[CB_PPL], ray[CB_PPL], rbx[CB_PPL], rby[CB_PPL];
    #pragma unroll
    for (int r = 0; r < CB_PPL; ++r) {
        int pp = wid * (32 * CB_PPL) + r * 32 + ln;
        rax[r] = sPack[pp * 4 + 0];
        ray[r] = sPack[pp * 4 + 1];
        rbx[r] = sPack[pp * 4 + 2];
        rby[r] = sPack[pp * 4 + 3];
    }

    float cmin[2 * CB_PPL];
    #pragma unroll
    for (int r = 0; r < 2 * CB_PPL; ++r) cmin[r] = 3.402823466e38f;

    // ---- main loop: 64 preds x 8 lane-targets ----
    for (int i = 0; i < CB_TI; ++i) {
        float4 q = sQ[i];                                   // LDS.128 broadcast
        unsigned long long q0  = f32x2_pack(q.x, q.x);
        unsigned long long q1  = f32x2_pack(q.y, q.y);
        unsigned long long q2  = f32x2_pack(q.z, q.z);
        unsigned long long xxp = f32x2_pack(q.w, q.w);

        float rm0 = 3.402823466e38f, rm1 = 3.402823466e38f;
        #pragma unroll
        for (int r = 0; r < CB_PPL; ++r) {
            unsigned long long t = f32x2_fma(q2, rbx[r], rby[r]);
            t = f32x2_fma(q1, ray[r], t);
            t = f32x2_fma(q0, rax[r], t);               // t = yy - 2 x.y
            unsigned long long u = f32x2_add(t, xxp);   // u = d^2
            float tl, th, ul, uh;
            f32x2_unpack(t, tl, th);
            f32x2_unpack(u, ul, uh);
            rm0 = fminf(rm0, tl);
            rm1 = fminf(rm1, th);
            cmin[2 * r]     = fminf(cmin[2 * r],     ul);
            cmin[2 * r + 1] = fminf(cmin[2 * r + 1], uh);
        }
        unsigned e = encP(fminf(rm0, rm1));
        e = __reduce_min_sync(0xffffffffu, e);          // REDUX.MIN.U32
        if (ln == 0) sRowE[i * CB_NW + wid] = e;
    }

    // ---- publish col minima (REDG.MAX on reversed encoding) ----
    unsigned* gc = g_col + (size_t)b * CB_NPTS;
    #pragma unroll
    for (int r = 0; r < CB_PPL; ++r) {
        int pp = wid * (32 * CB_PPL) + r * 32 + ln;
        atomicMax(&gc[2 * pp],     encR(cmin[2 * r]));
        atomicMax(&gc[2 * pp + 1], encR(cmin[2 * r + 1]));
    }

    __syncthreads();

    // ---- row side: combine 8 warps, add |x|^2, sum, one atomic per warp ----
    if (tid < CB_TI) {
        const unsigned* e = &sRowE[tid * CB_NW];
        unsigned m01 = min(e[0], e[1]), m23 = min(e[2], e[3]);
        unsigned m45 = min(e[4], e[5]), m67 = min(e[6], e[7]);
        unsigned em = min(min(m01, m23), min(m45, m67));
        float val = sQ[tid].w + decP(em);
        #pragma unroll
        for (int o = 16; o > 0; o >>= 1)
            val += __shfl_down_sync(0xffffffffu, val, o);
        if (ln == 0) atomicAdd(&g_rowsum, val);
    }
}

__global__ __launch_bounds__(128)
void chamfer_finalize(float* __restrict__ out)
{
    __shared__ float sRed[4];
    const int b = blockIdx.y;
    const int j = blockIdx.x * 128 + threadIdx.x;   // 16 blocks per batch
    unsigned* gc = g_col + (size_t)b * CB_NPTS;

    float acc = decR(gc[j]);
    gc[j] = 0u;                          // reset identity for next replay

    #pragma unroll
    for (int o = 16; o > 0; o >>= 1)
        acc += __shfl_down_sync(0xffffffffu, acc, o);
    if ((threadIdx.x & 31) == 0) sRed[threadIdx.x >> 5] = acc;
    __syncthreads();
    if (threadIdx.x == 0) {
        float v2 = sRed[0] + sRed[1] + sRed[2] + sRed[3];
        if (blockIdx.x == 0 && blockIdx.y == 0) {
            v2 += g_rowsum;              // consume row-side sum
            g_rowsum = 0.0f;             // reset for next replay
        }
        atomicAdd(out, v2);
    }
}

extern "C" void kernel_launch(void* const* d_in, const int* in_sizes, int n_in,
                              void* d_out, int out_size) {
    const float* preds = (const float*)d_in[0];
    const float* targs = (const float*)d_in[1];
    float* out = (float*)d_out;

    dim3 gridM(CB_ITILES, CB_B);        // (32, 16) = 512 blocks x 256 thr
    chamfer_main<<<gridM, CB_TPB>>>(preds, targs, out);

    dim3 gridF(CB_NPTS / 128, CB_B);    // (16, 16) = 256 blocks x 128 thr
    chamfer_finalize<<<gridF, 128>>>(out);
}